// round 2
// baseline (speedup 1.0000x reference)
#include <cuda_runtime.h>
#include <cuda_bf16.h>
#include <cstdint>

// Problem shape (fixed by the dataset).
constexpr int B = 32;
constexpr int A = 16384;
constexpr int C = 81;

// Scratch: per-anchor max_ce (already zeroed for depth!=0 anchors).
// Non-negative floats -> uint32 bit pattern is order-preserving.
__device__ float g_maxce[B * A];

// ---------------------------------------------------------------------------
// Kernel 1: elementwise BCE-with-logits + per-anchor max reduction.
// One warp per anchor (81 classes -> <=3 elements per lane).
// ---------------------------------------------------------------------------
__global__ void __launch_bounds__(256) ce_kernel(
    const float* __restrict__ pred,
    const float* __restrict__ tgt,
    const int*   __restrict__ depth,
    float*       __restrict__ out)
{
    const int warps_per_block = blockDim.x >> 5;
    const int g    = blockIdx.x * warps_per_block + (threadIdx.x >> 5); // anchor id
    const int lane = threadIdx.x & 31;
    if (g >= B * A) return;

    const size_t base = (size_t)g * C;
    float m = 0.0f;  // ce >= 0 always (softplus(x) >= t*x for t in [0,1])

#pragma unroll
    for (int i = 0; i < 3; i++) {
        const int c = lane + i * 32;
        if (c < C) {
            const float x = pred[base + c];
            const float t = tgt[base + c];
            // stable softplus: max(x,0) + log1p(exp(-|x|))
            const float ce = fmaxf(x, 0.0f) + log1pf(__expf(-fabsf(x))) - t * x;
            out[base + c] = ce;
            m = fmaxf(m, ce);
        }
    }

#pragma unroll
    for (int off = 16; off; off >>= 1)
        m = fmaxf(m, __shfl_xor_sync(0xffffffffu, m, off));

    if (lane == 0) {
        const int d = depth[g];
        g_maxce[g] = (d != 0) ? 0.0f : m;
    }
}

// ---------------------------------------------------------------------------
// Kernel 2: per-batch hard-negative selection + row zeroing.
// One block per batch. Replicates JAX stable double-argsort semantics:
//   rank_i = #{j : v_j > v_i} + #{j < i : v_j == v_i};  neg_i <=> rank_i < num_neg
// via radix-select of the num_neg-th largest value + stable tie prefix scan.
// ---------------------------------------------------------------------------
__global__ void __launch_bounds__(1024) mask_kernel(
    const int* __restrict__ depth,
    const int* __restrict__ npr_ptr,   // may be nullptr -> ratio = 3
    float*     __restrict__ out)
{
    const int b    = blockIdx.x;
    const int tid  = threadIdx.x;
    const int lane = tid & 31;
    const int wid  = tid >> 5;
    const unsigned FULL = 0xffffffffu;
    const int NT = 1024;

    const uint32_t* vrow = reinterpret_cast<const uint32_t*>(g_maxce) + (size_t)b * A;
    const int*      drow = depth + (size_t)b * A;

    __shared__ int s_hist[256];
    __shared__ int s_warp[32];
    __shared__ int s_sc[4];      // 0: block-reduce result, 1: remaining, 2: bin, 3: chunk tie total
    __shared__ int s_running;

    // ---- num_pos = count(depth > 0) ----
    int cnt = 0;
    for (int i = tid; i < A; i += NT) cnt += (drow[i] > 0);
#pragma unroll
    for (int off = 16; off; off >>= 1) cnt += __shfl_xor_sync(FULL, cnt, off);
    if (lane == 0) s_warp[wid] = cnt;
    __syncthreads();
    if (tid < 32) {
        int v = s_warp[tid];
#pragma unroll
        for (int off = 16; off; off >>= 1) v += __shfl_xor_sync(FULL, v, off);
        if (tid == 0) s_sc[0] = v;
    }
    __syncthreads();

    const int ratio   = npr_ptr ? *npr_ptr : 3;
    const int num_pos = s_sc[0];
    int num_neg = ratio * num_pos;
    if (num_neg > A - 1) num_neg = A - 1;
    if (num_neg < 0)     num_neg = 0;

    // ---- radix select: v* = num_neg-th largest value (1-indexed) ----
    uint32_t vstar  = 0;
    int      r_ties = 0;
    const bool have_neg = (num_neg > 0);

    if (have_neg) {
        if (tid == 0) s_sc[1] = num_neg;
        uint32_t prefix = 0, pmask = 0;
        for (int shift = 24; shift >= 0; shift -= 8) {
            __syncthreads();
            if (tid < 256) s_hist[tid] = 0;
            __syncthreads();
            for (int i = tid; i < A; i += NT) {
                const uint32_t v = vrow[i];
                if ((v & pmask) == prefix)
                    atomicAdd(&s_hist[(v >> shift) & 255], 1);
            }
            __syncthreads();
            if (tid == 0) {
                int rem = s_sc[1];
                int cum = 0;
                int bin;
                for (bin = 255; bin > 0; bin--) {
                    if (cum + s_hist[bin] >= rem) break;
                    cum += s_hist[bin];
                }
                s_sc[2] = bin;
                s_sc[1] = rem - cum;
            }
            __syncthreads();
            const int bin = s_sc[2];
            prefix |= ((uint32_t)bin) << shift;
            pmask  |= 0xFFu << shift;
        }
        vstar = prefix;

        // c_gt = count strictly greater than v*
        int cg = 0;
        for (int i = tid; i < A; i += NT) cg += (vrow[i] > vstar);
#pragma unroll
        for (int off = 16; off; off >>= 1) cg += __shfl_xor_sync(FULL, cg, off);
        __syncthreads();
        if (lane == 0) s_warp[wid] = cg;
        __syncthreads();
        if (tid < 32) {
            int v = s_warp[tid];
#pragma unroll
            for (int off = 16; off; off >>= 1) v += __shfl_xor_sync(FULL, v, off);
            if (tid == 0) s_sc[0] = v;
        }
        __syncthreads();
        r_ties = num_neg - s_sc[0];   // # of tied (== v*) anchors kept, in index order
    }

    if (tid == 0) s_running = 0;
    __syncthreads();

    // ---- stable tie prefix scan + zero masked-out rows ----
    for (int base = 0; base < A; base += NT) {
        const int i = base + tid;                 // A % NT == 0, no bounds check
        const uint32_t v = vrow[i];
        const int      d = drow[i];

        const bool tie = have_neg && (v == vstar);
        const unsigned bal = __ballot_sync(FULL, tie);
        const int ex = __popc(bal & ((1u << lane) - 1));
        if (lane == 0) s_warp[wid] = __popc(bal);
        __syncthreads();
        if (tid < 32) {
            const int orig = s_warp[tid];
            int sc = orig;
#pragma unroll
            for (int off = 1; off < 32; off <<= 1) {
                const int n = __shfl_up_sync(FULL, sc, off);
                if (lane >= off) sc += n;
            }
            s_warp[tid] = sc - orig;              // exclusive prefix of warp totals
            if (tid == 31) s_sc[3] = sc;          // chunk total
        }
        __syncthreads();

        const int  tie_idx = s_running + s_warp[wid] + ex;
        const bool neg  = have_neg && ((v > vstar) || (tie && tie_idx < r_ties));
        const bool keep = (d > 0) || neg;
        if (!keep) {
            float* row = out + ((size_t)b * A + i) * C;
#pragma unroll
            for (int c = 0; c < C; c++) row[c] = 0.0f;
        }
        __syncthreads();
        if (tid == 0) s_running += s_sc[3];
        __syncthreads();
    }
}

// ---------------------------------------------------------------------------
extern "C" void kernel_launch(void* const* d_in, const int* in_sizes, int n_in,
                              void* d_out, int out_size)
{
    const float* pred  = (const float*)d_in[0];
    const float* tgt   = (const float*)d_in[1];
    const int*   depth = (const int*)d_in[2];
    const int*   npr   = (n_in >= 4) ? (const int*)d_in[3] : nullptr;
    float* out = (float*)d_out;

    // Kernel 1: one warp per anchor, 8 warps per block.
    const int total_anchors = B * A;                 // 524288
    const int threads1 = 256;
    const int blocks1  = total_anchors / (threads1 / 32);
    ce_kernel<<<blocks1, threads1>>>(pred, tgt, depth, out);

    // Kernel 2: one block per batch.
    mask_kernel<<<B, 1024>>>(depth, npr, out);
}

// round 3
// speedup vs baseline: 1.1054x; 1.1054x over previous
#include <cuda_runtime.h>
#include <cuda_bf16.h>
#include <cstdint>

constexpr int B = 32;
constexpr int A = 16384;
constexpr int C = 81;

// Per-anchor max_ce (zeroed for depth!=0). Non-negative floats -> uint32 bits
// are order-preserving.
__device__ float g_maxce[B * A];

// ---------------------------------------------------------------------------
// Kernel 1: BCE-with-logits + per-anchor max.
// 32 anchors per block = 2592 floats = 648 float4 (block range is 128B-aligned:
// 32*324B = 81*128B). Fully vectorized global traffic; max via smem.
// ---------------------------------------------------------------------------
constexpr int APB  = 32;                 // anchors per block
constexpr int FPB  = APB * C;            // 2592 floats
constexpr int V4PB = FPB / 4;            // 648 float4

__device__ __forceinline__ float bce(float x, float t) {
    // stable softplus(x) - t*x
    return fmaxf(x, 0.0f) + log1pf(__expf(-fabsf(x))) - t * x;
}

__global__ void __launch_bounds__(256) ce_kernel(
    const float* __restrict__ pred,
    const float* __restrict__ tgt,
    const int*   __restrict__ depth,
    float*       __restrict__ out)
{
    __shared__ float s_ce[FPB];

    const size_t base4 = (size_t)blockIdx.x * V4PB;
    const float4* __restrict__ p4 = reinterpret_cast<const float4*>(pred) + base4;
    const float4* __restrict__ t4 = reinterpret_cast<const float4*>(tgt)  + base4;
    float4* __restrict__ o4 = reinterpret_cast<float4*>(out) + base4;

    // Phase 1: vectorized elementwise ce, write to gmem + smem.
    for (int j = threadIdx.x; j < V4PB; j += 256) {
        const float4 x = p4[j];
        const float4 t = t4[j];
        float4 ce;
        ce.x = bce(x.x, t.x);
        ce.y = bce(x.y, t.y);
        ce.z = bce(x.z, t.z);
        ce.w = bce(x.w, t.w);
        o4[j] = ce;
        *reinterpret_cast<float4*>(&s_ce[j * 4]) = ce;
    }
    __syncthreads();

    // Phase 2: per-anchor max (warp per anchor, 8 warps x 4 anchors).
    const int lane = threadIdx.x & 31;
    const int wid  = threadIdx.x >> 5;
    const int gbase = blockIdx.x * APB;

#pragma unroll
    for (int k = 0; k < APB / 8; k++) {
        const int a = wid + k * 8;
        float m = s_ce[a * C + lane];                       // lane < 81 always
        if (lane + 32 < C) m = fmaxf(m, s_ce[a * C + lane + 32]);
        if (lane + 64 < C) m = fmaxf(m, s_ce[a * C + lane + 64]);
#pragma unroll
        for (int off = 16; off; off >>= 1)
            m = fmaxf(m, __shfl_xor_sync(0xffffffffu, m, off));
        if (lane == 0) {
            const int g = gbase + a;
            g_maxce[g] = (depth[g] != 0) ? 0.0f : m;
        }
    }
}

// ---------------------------------------------------------------------------
// Kernel 2: per-batch hard-negative selection + row zeroing.
// One block of 1024 threads per batch; each thread owns 16 CONTIGUOUS anchors
// held in registers. Radix select = 16 passes x 2 bits, counts packed in a
// u64 and block-reduced with shuffles (no atomics, one memory pass total).
// ---------------------------------------------------------------------------
__global__ void __launch_bounds__(1024) mask_kernel(
    const int* __restrict__ depth,
    const int* __restrict__ npr_ptr,
    float*     __restrict__ out)
{
    const int b    = blockIdx.x;
    const int tid  = threadIdx.x;
    const int lane = tid & 31;
    const int wid  = tid >> 5;
    const unsigned FULL = 0xffffffffu;

    __shared__ unsigned long long s_red[32];
    __shared__ int s_scan[32];
    __shared__ int s_bcast;

    // ---- load my 16 contiguous values + depth bits into registers ----
    const uint32_t* vrow = reinterpret_cast<const uint32_t*>(g_maxce) + (size_t)b * A;
    const int*      drow = depth + (size_t)b * A;

    uint32_t v[16];
    const uint4* vv = reinterpret_cast<const uint4*>(vrow) + tid * 4;
#pragma unroll
    for (int q = 0; q < 4; q++) {
        const uint4 u = vv[q];
        v[q * 4 + 0] = u.x; v[q * 4 + 1] = u.y; v[q * 4 + 2] = u.z; v[q * 4 + 3] = u.w;
    }
    unsigned dmask = 0;
    const int4* dd = reinterpret_cast<const int4*>(drow) + tid * 4;
#pragma unroll
    for (int q = 0; q < 4; q++) {
        const int4 u = dd[q];
        dmask |= (unsigned)(u.x > 0) << (q * 4 + 0);
        dmask |= (unsigned)(u.y > 0) << (q * 4 + 1);
        dmask |= (unsigned)(u.z > 0) << (q * 4 + 2);
        dmask |= (unsigned)(u.w > 0) << (q * 4 + 3);
    }

    // ---- num_pos (block reduce) ----
    {
        int cnt = __popc(dmask);
#pragma unroll
        for (int off = 16; off; off >>= 1) cnt += __shfl_xor_sync(FULL, cnt, off);
        if (lane == 0) s_scan[wid] = cnt;
        __syncthreads();
        if (wid == 0) {
            int y = s_scan[lane];
#pragma unroll
            for (int off = 16; off; off >>= 1) y += __shfl_xor_sync(FULL, y, off);
            if (lane == 0) s_bcast = y;
        }
        __syncthreads();
    }
    const int ratio   = npr_ptr ? *npr_ptr : 3;
    const int num_pos = s_bcast;
    int num_neg = ratio * num_pos;
    if (num_neg > A - 1) num_neg = A - 1;
    if (num_neg < 0)     num_neg = 0;
    const bool have_neg = (num_neg > 0);
    __syncthreads();

    // ---- radix select (2 bits / pass): vstar = num_neg-th largest ----
    uint32_t vstar = 0;
    int r_ties = 0;
    if (have_neg) {
        uint32_t prefix = 0, pmask = 0;
        int rem = num_neg;
#pragma unroll
        for (int bit = 30; bit >= 0; bit -= 2) {
            unsigned long long pc = 0;
#pragma unroll
            for (int j = 0; j < 16; j++) {
                if ((v[j] & pmask) == prefix) {
                    const unsigned two = (v[j] >> bit) & 3u;
                    pc += (two == 3u) ? (1ull << 42)
                        : (two == 2u) ? (1ull << 21)
                        : (two == 1u) ? 1ull : 0ull;
                }
            }
            // block reduce pc
#pragma unroll
            for (int off = 16; off; off >>= 1) pc += __shfl_xor_sync(FULL, pc, off);
            if (lane == 0) s_red[wid] = pc;
            __syncthreads();
            if (wid == 0) {
                unsigned long long y = s_red[lane];
#pragma unroll
                for (int off = 16; off; off >>= 1) y += __shfl_xor_sync(FULL, y, off);
                if (lane == 0) s_red[0] = y;
            }
            __syncthreads();
            pc = s_red[0];
            __syncthreads();

            const int c3 = (int)((pc >> 42) & 0x1FFFFF);
            const int c2 = (int)((pc >> 21) & 0x1FFFFF);
            const int c1 = (int)( pc        & 0x1FFFFF);
            uint32_t sel;
            if      (c3 >= rem)           { sel = 3u; }
            else if (c3 + c2 >= rem)      { sel = 2u; rem -= c3; }
            else if (c3 + c2 + c1 >= rem) { sel = 1u; rem -= c3 + c2; }
            else                          { sel = 0u; rem -= c3 + c2 + c1; }
            prefix |= sel << bit;
            pmask  |= 3u << bit;
        }
        vstar  = prefix;
        r_ties = rem;           // = num_neg - c_gt, guaranteed 1..c_eq
    }

    // ---- stable tie rank: exclusive block scan of per-thread tie counts ----
    int myties = 0;
    if (have_neg) {
#pragma unroll
        for (int j = 0; j < 16; j++) myties += (v[j] == vstar);
    }
    int ws = myties;
#pragma unroll
    for (int off = 1; off < 32; off <<= 1) {
        const int n = __shfl_up_sync(FULL, ws, off);
        if (lane >= off) ws += n;
    }
    if (lane == 31) s_scan[wid] = ws;
    __syncthreads();
    if (wid == 0) {
        int y = s_scan[lane];
        int z = y;
#pragma unroll
        for (int off = 1; off < 32; off <<= 1) {
            const int n = __shfl_up_sync(FULL, z, off);
            if (lane >= off) z += n;
        }
        s_scan[lane] = z - y;   // exclusive prefix of warp totals
    }
    __syncthreads();
    int tie_idx = s_scan[wid] + (ws - myties);   // my exclusive tie base

    // ---- apply mask: zero rows with !( depth>0 | neg ) ----
    const int abase = tid * 16;
#pragma unroll
    for (int j = 0; j < 16; j++) {
        const bool tie = have_neg && (v[j] == vstar);
        const bool neg = have_neg && ((v[j] > vstar) || (tie && tie_idx < r_ties));
        if (tie) tie_idx++;
        const bool keep = ((dmask >> j) & 1u) || neg;
        if (!keep) {
            float* row = out + ((size_t)b * A + abase + j) * C;
#pragma unroll
            for (int c = 0; c < C; c++) row[c] = 0.0f;
        }
    }
}

// ---------------------------------------------------------------------------
extern "C" void kernel_launch(void* const* d_in, const int* in_sizes, int n_in,
                              void* d_out, int out_size)
{
    const float* pred  = (const float*)d_in[0];
    const float* tgt   = (const float*)d_in[1];
    const int*   depth = (const int*)d_in[2];
    const int*   npr   = (n_in >= 4) ? (const int*)d_in[3] : nullptr;
    float* out = (float*)d_out;

    const int blocks1 = (B * A) / APB;   // 16384
    ce_kernel<<<blocks1, 256>>>(pred, tgt, depth, out);
    mask_kernel<<<B, 1024>>>(depth, npr, out);
}

// round 4
// speedup vs baseline: 1.4883x; 1.3463x over previous
#include <cuda_runtime.h>
#include <cuda_bf16.h>
#include <cstdint>

constexpr int B = 32;
constexpr int A = 16384;
constexpr int C = 81;

constexpr int APB  = 32;            // anchors per ce block
constexpr int FPB  = APB * C;       // 2592 floats
constexpr int V4PB = FPB / 4;       // 648 float4
constexpr int WPB  = A / 32;        // 512 mask words per batch
constexpr int BPB  = A / APB;       // 512 ce blocks per batch

// Scratch (device globals; no allocations allowed).
__device__ float    g_maxce[B * A];         // slow path only
__device__ unsigned g_posmask[B * WPB];     // bit: depth > 0
__device__ unsigned g_zeromask[B * WPB];    // bit: v == 0  (v = masked max_ce)
__device__ int      g_npos[B];
__device__ int      g_cgt[B];               // count(v > 0)

// ---------------------------------------------------------------------------
__global__ void init_kernel() {
    if (threadIdx.x < B) { g_npos[threadIdx.x] = 0; g_cgt[threadIdx.x] = 0; }
}

// ---------------------------------------------------------------------------
// Kernel 1: BCE-with-logits + per-anchor max + per-batch stats.
// 32 anchors/block = 648 float4 (128B-aligned block ranges).
// ---------------------------------------------------------------------------
__device__ __forceinline__ float bce(float x, float t) {
    return fmaxf(x, 0.0f) + log1pf(__expf(-fabsf(x))) - t * x;
}

__global__ void __launch_bounds__(256) ce_kernel(
    const float* __restrict__ pred,
    const float* __restrict__ tgt,
    const int*   __restrict__ depth,
    float*       __restrict__ out)
{
    __shared__ float s_ce[FPB];
    __shared__ float s_m[APB];

    const size_t base4 = (size_t)blockIdx.x * V4PB;
    const float4* __restrict__ p4 = reinterpret_cast<const float4*>(pred) + base4;
    const float4* __restrict__ t4 = reinterpret_cast<const float4*>(tgt)  + base4;
    float4* __restrict__ o4 = reinterpret_cast<float4*>(out) + base4;

    for (int j = threadIdx.x; j < V4PB; j += 256) {
        const float4 x = p4[j];
        const float4 t = t4[j];
        float4 ce;
        ce.x = bce(x.x, t.x);
        ce.y = bce(x.y, t.y);
        ce.z = bce(x.z, t.z);
        ce.w = bce(x.w, t.w);
        o4[j] = ce;
        *reinterpret_cast<float4*>(&s_ce[j * 4]) = ce;
    }
    __syncthreads();

    const int lane  = threadIdx.x & 31;
    const int wid   = threadIdx.x >> 5;
    const int gbase = blockIdx.x * APB;

#pragma unroll
    for (int k = 0; k < APB / 8; k++) {
        const int a = wid + k * 8;
        float m = s_ce[a * C + lane];
        if (lane + 32 < C) m = fmaxf(m, s_ce[a * C + lane + 32]);
        if (lane + 64 < C) m = fmaxf(m, s_ce[a * C + lane + 64]);
#pragma unroll
        for (int off = 16; off; off >>= 1)
            m = fmaxf(m, __shfl_xor_sync(0xffffffffu, m, off));
        if (lane == 0) {
            const int g = gbase + a;
            const float meff = (depth[g] != 0) ? 0.0f : m;
            g_maxce[g] = meff;
            s_m[a] = meff;
        }
    }
    __syncthreads();

    // Warp 0: per-block ballots + per-batch counters.
    if (wid == 0) {
        const int g = gbase + lane;
        const int d = depth[g];
        const float mv = s_m[lane];
        const unsigned posb  = __ballot_sync(0xffffffffu, d > 0);
        const unsigned zerob = __ballot_sync(0xffffffffu, mv == 0.0f);
        if (lane == 0) {
            g_posmask[blockIdx.x]  = posb;
            g_zeromask[blockIdx.x] = zerob;
            const int batch = blockIdx.x / BPB;
            atomicAdd(&g_npos[batch], __popc(posb));
            atomicAdd(&g_cgt[batch], 32 - __popc(zerob));
        }
    }
}

// ---------------------------------------------------------------------------
// Kernel 2: per-batch hard-negative selection + row zeroing. Block per batch.
// Fast path (num_neg > count(v>0)): v* = 0; only bitmasks needed (4 KB/batch).
// Slow path: register radix select over g_maxce (general correctness).
// ---------------------------------------------------------------------------
__global__ void __launch_bounds__(1024) mask_kernel(
    const int* __restrict__ npr_ptr,
    float*     __restrict__ out)
{
    const int b    = blockIdx.x;
    const int tid  = threadIdx.x;
    const int lane = tid & 31;
    const int wid  = tid >> 5;
    const unsigned FULL = 0xffffffffu;

    __shared__ unsigned long long s_red[32];
    __shared__ int s_scan[32];

    const int ratio   = npr_ptr ? *npr_ptr : 3;
    const int num_pos = g_npos[b];
    const int cgt     = g_cgt[b];
    int num_neg = ratio * num_pos;
    if (num_neg > A - 1) num_neg = A - 1;
    if (num_neg < 0)     num_neg = 0;

    if (num_neg == 0 || num_neg > cgt) {
        // ---------------- FAST PATH: vstar == 0 (or no negatives) ----------
        const bool have_neg = (num_neg > 0);
        const int  r_ties   = have_neg ? (num_neg - cgt) : 0;

        unsigned zb = 0, pb = 0;
        int myz = 0;
        if (tid < WPB) {
            zb  = g_zeromask[b * WPB + tid];
            pb  = g_posmask[b * WPB + tid];
            myz = __popc(zb);
        }
        // exclusive block scan of myz (threads >= WPB contribute 0)
        int ws = myz;
#pragma unroll
        for (int off = 1; off < 32; off <<= 1) {
            const int n = __shfl_up_sync(FULL, ws, off);
            if (lane >= off) ws += n;
        }
        if (lane == 31) s_scan[wid] = ws;
        __syncthreads();
        if (wid == 0) {
            const int y = s_scan[lane];
            int z = y;
#pragma unroll
            for (int off = 1; off < 32; off <<= 1) {
                const int n = __shfl_up_sync(FULL, z, off);
                if (lane >= off) z += n;
            }
            s_scan[lane] = z - y;
        }
        __syncthreads();

        if (tid < WPB) {
            const int zbase = s_scan[wid] + (ws - myz);  // exclusive zero-rank base
            const int abase = tid * 32;                  // anchor offset in batch
#pragma unroll 4
            for (int bit = 0; bit < 32; bit++) {
                const bool zero = (zb >> bit) & 1u;
                const bool pos  = (pb >> bit) & 1u;
                bool neg;
                if (!have_neg)   neg = false;
                else if (!zero)  neg = true;             // v > 0 > vstar
                else             neg = (zbase + __popc(zb & ((1u << bit) - 1))) < r_ties;
                if (!(pos || neg)) {
                    float* row = out + ((size_t)b * A + abase + bit) * C;
#pragma unroll
                    for (int c = 0; c < C; c++) row[c] = 0.0f;
                }
            }
        }
        return;
    }

    // ---------------- SLOW PATH: general radix select (0 < num_neg <= cgt) --
    const uint32_t* vrow = reinterpret_cast<const uint32_t*>(g_maxce) + (size_t)b * A;

    uint32_t v[16];
    const uint4* vv = reinterpret_cast<const uint4*>(vrow) + tid * 4;
#pragma unroll
    for (int q = 0; q < 4; q++) {
        const uint4 u = vv[q];
        v[q * 4 + 0] = u.x; v[q * 4 + 1] = u.y; v[q * 4 + 2] = u.z; v[q * 4 + 3] = u.w;
    }
    unsigned pmaskbits = 0;
    {
        const unsigned pw = g_posmask[b * WPB + (tid >> 1)];
        pmaskbits = (pw >> ((tid & 1) * 16)) & 0xFFFFu;   // my 16 anchors' pos bits
    }

    uint32_t vstar = 0;
    int r_ties = 0;
    {
        uint32_t prefix = 0, pmask = 0;
        int rem = num_neg;
#pragma unroll
        for (int bit = 30; bit >= 0; bit -= 2) {
            unsigned long long pc = 0;
#pragma unroll
            for (int j = 0; j < 16; j++) {
                if ((v[j] & pmask) == prefix) {
                    const unsigned two = (v[j] >> bit) & 3u;
                    pc += (two == 3u) ? (1ull << 42)
                        : (two == 2u) ? (1ull << 21)
                        : (two == 1u) ? 1ull : 0ull;
                }
            }
#pragma unroll
            for (int off = 16; off; off >>= 1) pc += __shfl_xor_sync(FULL, pc, off);
            if (lane == 0) s_red[wid] = pc;
            __syncthreads();
            if (wid == 0) {
                unsigned long long y = s_red[lane];
#pragma unroll
                for (int off = 16; off; off >>= 1) y += __shfl_xor_sync(FULL, y, off);
                if (lane == 0) s_red[0] = y;
            }
            __syncthreads();
            pc = s_red[0];
            __syncthreads();

            const int c3 = (int)((pc >> 42) & 0x1FFFFF);
            const int c2 = (int)((pc >> 21) & 0x1FFFFF);
            const int c1 = (int)( pc        & 0x1FFFFF);
            uint32_t sel;
            if      (c3 >= rem)           { sel = 3u; }
            else if (c3 + c2 >= rem)      { sel = 2u; rem -= c3; }
            else if (c3 + c2 + c1 >= rem) { sel = 1u; rem -= c3 + c2; }
            else                          { sel = 0u; rem -= c3 + c2 + c1; }
            prefix |= sel << bit;
            pmask  |= 3u << bit;
        }
        vstar  = prefix;
        r_ties = rem;
    }

    // stable tie rank: exclusive block scan of per-thread tie counts
    int myties = 0;
#pragma unroll
    for (int j = 0; j < 16; j++) myties += (v[j] == vstar);
    int ws = myties;
#pragma unroll
    for (int off = 1; off < 32; off <<= 1) {
        const int n = __shfl_up_sync(FULL, ws, off);
        if (lane >= off) ws += n;
    }
    if (lane == 31) s_scan[wid] = ws;
    __syncthreads();
    if (wid == 0) {
        const int y = s_scan[lane];
        int z = y;
#pragma unroll
        for (int off = 1; off < 32; off <<= 1) {
            const int n = __shfl_up_sync(FULL, z, off);
            if (lane >= off) z += n;
        }
        s_scan[lane] = z - y;
    }
    __syncthreads();
    int tie_idx = s_scan[wid] + (ws - myties);

    const int abase = tid * 16;
#pragma unroll
    for (int j = 0; j < 16; j++) {
        const bool tie = (v[j] == vstar);
        const bool neg = (v[j] > vstar) || (tie && tie_idx < r_ties);
        if (tie) tie_idx++;
        const bool keep = ((pmaskbits >> j) & 1u) || neg;
        if (!keep) {
            float* row = out + ((size_t)b * A + abase + j) * C;
#pragma unroll
            for (int c = 0; c < C; c++) row[c] = 0.0f;
        }
    }
}

// ---------------------------------------------------------------------------
extern "C" void kernel_launch(void* const* d_in, const int* in_sizes, int n_in,
                              void* d_out, int out_size)
{
    const float* pred  = (const float*)d_in[0];
    const float* tgt   = (const float*)d_in[1];
    const int*   depth = (const int*)d_in[2];
    const int*   npr   = (n_in >= 4) ? (const int*)d_in[3] : nullptr;
    float* out = (float*)d_out;

    init_kernel<<<1, 64>>>();
    ce_kernel<<<(B * A) / APB, 256>>>(pred, tgt, depth, out);
    mask_kernel<<<B, 1024>>>(npr, out);
}

// round 5
// speedup vs baseline: 1.6232x; 1.0907x over previous
#include <cuda_runtime.h>
#include <cuda_bf16.h>
#include <cstdint>

constexpr int B = 32;
constexpr int A = 16384;
constexpr int C = 81;

constexpr int APB  = 32;            // anchors per ce block
constexpr int FPB  = APB * C;       // 2592 floats
constexpr int V4PB = FPB / 4;       // 648 float4
constexpr int WPB  = A / 32;        // 512 mask words per batch

// Scratch (device globals; no allocations allowed).
__device__ float    g_maxce[B * A];         // slow path only
__device__ unsigned g_posmask[B * WPB];     // bit: depth > 0
__device__ unsigned g_zeromask[B * WPB];    // bit: v == 0  (v = masked max_ce)

// ---------------------------------------------------------------------------
__device__ __forceinline__ float bce(float x, float t) {
    return fmaxf(x, 0.0f) + log1pf(__expf(-fabsf(x))) - t * x;
}
__device__ __forceinline__ float4 bce4(float4 x, float4 t) {
    float4 r;
    r.x = bce(x.x, t.x); r.y = bce(x.y, t.y);
    r.z = bce(x.z, t.z); r.w = bce(x.w, t.w);
    return r;
}

// ---------------------------------------------------------------------------
// Kernel 1: BCE-with-logits + per-anchor max + per-batch bitmasks.
// 32 anchors/block = 648 float4 (128B-aligned block ranges). Loads are
// front-batched (up to 6 LDG.128 in flight) to maximize DRAM MLP.
// ---------------------------------------------------------------------------
__global__ void __launch_bounds__(256) ce_kernel(
    const float* __restrict__ pred,
    const float* __restrict__ tgt,
    const int*   __restrict__ depth,
    float*       __restrict__ out)
{
    __shared__ float s_ce[FPB];
    __shared__ float s_m[APB];

    const int tid = threadIdx.x;
    const size_t base4 = (size_t)blockIdx.x * V4PB;
    const float4* __restrict__ p4 = reinterpret_cast<const float4*>(pred) + base4;
    const float4* __restrict__ t4 = reinterpret_cast<const float4*>(tgt)  + base4;
    float4* __restrict__ o4 = reinterpret_cast<float4*>(out) + base4;

    // Front-batched loads: 648 = 256 + 256 + 136.
    const bool has2 = (tid + 512) < V4PB;
    const float4 x0 = __ldcs(&p4[tid]);
    const float4 T0 = __ldcs(&t4[tid]);
    const float4 x1 = __ldcs(&p4[tid + 256]);
    const float4 T1 = __ldcs(&t4[tid + 256]);
    float4 x2, T2;
    if (has2) { x2 = __ldcs(&p4[tid + 512]); T2 = __ldcs(&t4[tid + 512]); }

    const float4 c0 = bce4(x0, T0);
    __stcs(&o4[tid], c0);
    *reinterpret_cast<float4*>(&s_ce[tid * 4]) = c0;

    const float4 c1 = bce4(x1, T1);
    __stcs(&o4[tid + 256], c1);
    *reinterpret_cast<float4*>(&s_ce[(tid + 256) * 4]) = c1;

    if (has2) {
        const float4 c2 = bce4(x2, T2);
        __stcs(&o4[tid + 512], c2);
        *reinterpret_cast<float4*>(&s_ce[(tid + 512) * 4]) = c2;
    }
    __syncthreads();

    const int lane  = tid & 31;
    const int wid   = tid >> 5;
    const int gbase = blockIdx.x * APB;

#pragma unroll
    for (int k = 0; k < APB / 8; k++) {
        const int a = wid + k * 8;
        float m = s_ce[a * C + lane];
        if (lane + 32 < C) m = fmaxf(m, s_ce[a * C + lane + 32]);
        if (lane + 64 < C) m = fmaxf(m, s_ce[a * C + lane + 64]);
#pragma unroll
        for (int off = 16; off; off >>= 1)
            m = fmaxf(m, __shfl_xor_sync(0xffffffffu, m, off));
        if (lane == 0) {
            const int g = gbase + a;
            const float meff = (depth[g] != 0) ? 0.0f : m;
            g_maxce[g] = meff;
            s_m[a] = meff;
        }
    }
    __syncthreads();

    // Warp 0: per-block ballots -> bitmasks (no atomics).
    if (wid == 0) {
        const int g = gbase + lane;
        const int d = depth[g];
        const float mv = s_m[lane];
        const unsigned posb  = __ballot_sync(0xffffffffu, d > 0);
        const unsigned zerob = __ballot_sync(0xffffffffu, mv == 0.0f);
        if (lane == 0) {
            g_posmask[blockIdx.x]  = posb;
            g_zeromask[blockIdx.x] = zerob;
        }
    }
}

// ---------------------------------------------------------------------------
// Kernel 2: per-batch hard-negative selection + row zeroing. Block per batch.
// Stats (num_pos, cgt) computed here from the 4 KB bitmasks (no init kernel).
// Fast path (num_neg > cgt): v* = 0; only bitmasks needed.
// Slow path: register radix select over g_maxce (general correctness).
// ---------------------------------------------------------------------------
__global__ void __launch_bounds__(1024) mask_kernel(
    const int* __restrict__ npr_ptr,
    float*     __restrict__ out)
{
    const int b    = blockIdx.x;
    const int tid  = threadIdx.x;
    const int lane = tid & 31;
    const int wid  = tid >> 5;
    const unsigned FULL = 0xffffffffu;

    __shared__ unsigned long long s_red[32];
    __shared__ int s_scan[32];
    __shared__ int s_stats;

    // ---- load bitmasks + stats reduce (num_pos | cgt<<16 packed) ----
    unsigned pb = 0, zb = 0;
    if (tid < WPB) {
        pb = g_posmask[b * WPB + tid];
        zb = g_zeromask[b * WPB + tid];
    }
    {
        int pack = __popc(pb) | ((tid < WPB ? 32 - __popc(zb) : 0) << 16);
#pragma unroll
        for (int off = 16; off; off >>= 1) pack += __shfl_xor_sync(FULL, pack, off);
        if (lane == 0) s_scan[wid] = pack;
        __syncthreads();
        if (wid == 0) {
            int y = s_scan[lane];
#pragma unroll
            for (int off = 16; off; off >>= 1) y += __shfl_xor_sync(FULL, y, off);
            if (lane == 0) s_stats = y;
        }
        __syncthreads();
    }
    const int num_pos = s_stats & 0xFFFF;
    const int cgt     = s_stats >> 16;

    const int ratio = npr_ptr ? *npr_ptr : 3;
    int num_neg = ratio * num_pos;
    if (num_neg > A - 1) num_neg = A - 1;
    if (num_neg < 0)     num_neg = 0;
    __syncthreads();

    if (num_neg == 0 || num_neg > cgt) {
        // ---------------- FAST PATH: vstar == 0 (or no negatives) ----------
        const bool have_neg = (num_neg > 0);
        const int  r_ties   = have_neg ? (num_neg - cgt) : 0;

        const int myz = (tid < WPB) ? __popc(zb) : 0;
        // exclusive block scan of myz
        int ws = myz;
#pragma unroll
        for (int off = 1; off < 32; off <<= 1) {
            const int n = __shfl_up_sync(FULL, ws, off);
            if (lane >= off) ws += n;
        }
        if (lane == 31) s_scan[wid] = ws;
        __syncthreads();
        if (wid == 0) {
            const int y = s_scan[lane];
            int z = y;
#pragma unroll
            for (int off = 1; off < 32; off <<= 1) {
                const int n = __shfl_up_sync(FULL, z, off);
                if (lane >= off) z += n;
            }
            s_scan[lane] = z - y;
        }
        __syncthreads();

        if (tid < WPB) {
            const int zbase = s_scan[wid] + (ws - myz);  // exclusive zero-rank base
            const int abase = tid * 32;
#pragma unroll 4
            for (int bit = 0; bit < 32; bit++) {
                const bool zero = (zb >> bit) & 1u;
                const bool pos  = (pb >> bit) & 1u;
                bool neg;
                if (!have_neg)   neg = false;
                else if (!zero)  neg = true;             // v > 0 > vstar
                else             neg = (zbase + __popc(zb & ((1u << bit) - 1))) < r_ties;
                if (!(pos || neg)) {
                    float* row = out + ((size_t)b * A + abase + bit) * C;
#pragma unroll
                    for (int c = 0; c < C; c++) row[c] = 0.0f;
                }
            }
        }
        return;
    }

    // ---------------- SLOW PATH: general radix select (0 < num_neg <= cgt) --
    const uint32_t* vrow = reinterpret_cast<const uint32_t*>(g_maxce) + (size_t)b * A;

    uint32_t v[16];
    const uint4* vv = reinterpret_cast<const uint4*>(vrow) + tid * 4;
#pragma unroll
    for (int q = 0; q < 4; q++) {
        const uint4 u = vv[q];
        v[q * 4 + 0] = u.x; v[q * 4 + 1] = u.y; v[q * 4 + 2] = u.z; v[q * 4 + 3] = u.w;
    }
    unsigned pmaskbits;
    {
        const unsigned pw = g_posmask[b * WPB + (tid >> 1)];
        pmaskbits = (pw >> ((tid & 1) * 16)) & 0xFFFFu;   // my 16 anchors' pos bits
    }

    uint32_t vstar = 0;
    int r_ties = 0;
    {
        uint32_t prefix = 0, pmask = 0;
        int rem = num_neg;
#pragma unroll
        for (int bit = 30; bit >= 0; bit -= 2) {
            unsigned long long pc = 0;
#pragma unroll
            for (int j = 0; j < 16; j++) {
                if ((v[j] & pmask) == prefix) {
                    const unsigned two = (v[j] >> bit) & 3u;
                    pc += (two == 3u) ? (1ull << 42)
                        : (two == 2u) ? (1ull << 21)
                        : (two == 1u) ? 1ull : 0ull;
                }
            }
#pragma unroll
            for (int off = 16; off; off >>= 1) pc += __shfl_xor_sync(FULL, pc, off);
            if (lane == 0) s_red[wid] = pc;
            __syncthreads();
            if (wid == 0) {
                unsigned long long y = s_red[lane];
#pragma unroll
                for (int off = 16; off; off >>= 1) y += __shfl_xor_sync(FULL, y, off);
                if (lane == 0) s_red[0] = y;
            }
            __syncthreads();
            pc = s_red[0];
            __syncthreads();

            const int c3 = (int)((pc >> 42) & 0x1FFFFF);
            const int c2 = (int)((pc >> 21) & 0x1FFFFF);
            const int c1 = (int)( pc        & 0x1FFFFF);
            uint32_t sel;
            if      (c3 >= rem)           { sel = 3u; }
            else if (c3 + c2 >= rem)      { sel = 2u; rem -= c3; }
            else if (c3 + c2 + c1 >= rem) { sel = 1u; rem -= c3 + c2; }
            else                          { sel = 0u; rem -= c3 + c2 + c1; }
            prefix |= sel << bit;
            pmask  |= 3u << bit;
        }
        vstar  = prefix;
        r_ties = rem;
    }

    // stable tie rank: exclusive block scan of per-thread tie counts
    int myties = 0;
#pragma unroll
    for (int j = 0; j < 16; j++) myties += (v[j] == vstar);
    int ws = myties;
#pragma unroll
    for (int off = 1; off < 32; off <<= 1) {
        const int n = __shfl_up_sync(FULL, ws, off);
        if (lane >= off) ws += n;
    }
    if (lane == 31) s_scan[wid] = ws;
    __syncthreads();
    if (wid == 0) {
        const int y = s_scan[lane];
        int z = y;
#pragma unroll
        for (int off = 1; off < 32; off <<= 1) {
            const int n = __shfl_up_sync(FULL, z, off);
            if (lane >= off) z += n;
        }
        s_scan[lane] = z - y;
    }
    __syncthreads();
    int tie_idx = s_scan[wid] + (ws - myties);

    const int abase = tid * 16;
#pragma unroll
    for (int j = 0; j < 16; j++) {
        const bool tie = (v[j] == vstar);
        const bool neg = (v[j] > vstar) || (tie && tie_idx < r_ties);
        if (tie) tie_idx++;
        const bool keep = ((pmaskbits >> j) & 1u) || neg;
        if (!keep) {
            float* row = out + ((size_t)b * A + abase + j) * C;
#pragma unroll
            for (int c = 0; c < C; c++) row[c] = 0.0f;
        }
    }
}

// ---------------------------------------------------------------------------
extern "C" void kernel_launch(void* const* d_in, const int* in_sizes, int n_in,
                              void* d_out, int out_size)
{
    const float* pred  = (const float*)d_in[0];
    const float* tgt   = (const float*)d_in[1];
    const int*   depth = (const int*)d_in[2];
    const int*   npr   = (n_in >= 4) ? (const int*)d_in[3] : nullptr;
    float* out = (float*)d_out;

    ce_kernel<<<(B * A) / APB, 256>>>(pred, tgt, depth, out);
    mask_kernel<<<B, 1024>>>(npr, out);
}